// round 4
// baseline (speedup 1.0000x reference)
#include <cuda_runtime.h>
#include <math.h>

#define SQ    2048
#define HIDD  2048
#define NH    16
#define NOPE  128
#define ROPE  64
#define VDIM  128
#define QD    192   // NOPE + ROPE
#define QLR   1536
#define KVLR  512
#define KVDN  576   // KVLR + ROPE

// ---------------- scratch (static device globals; no allocation) ----------------
__device__ __align__(256) float g_qc [SQ * QLR];
__device__ __align__(256) float g_kvd[SQ * KVDN];
__device__ __align__(256) float g_q  [SQ * NH * QD];
__device__ __align__(256) float g_kv [SQ * NH * (NOPE + VDIM)];
__device__ __align__(256) float g_qall[(long long)NH * SQ * QD];
__device__ __align__(256) float g_kall[(long long)NH * SQ * QD];
__device__ __align__(256) float g_v  [(long long)NH * SQ * VDIM];
__device__ __align__(256) float g_ctx[SQ * NH * VDIM];
__device__ __align__(256) float g_cos[SQ * 32];
__device__ __align__(256) float g_sin[SQ * 32];

// ---- packed f32x2 helpers (Blackwell sm_103a; FFMA2 only reachable via PTX) ----
__device__ __forceinline__ unsigned long long dup2(float v) {
    unsigned long long r;
    asm("mov.b64 %0, {%1, %1};" : "=l"(r) : "f"(v));
    return r;
}
__device__ __forceinline__ void fma2(unsigned long long& d,
                                     unsigned long long a, unsigned long long b) {
    asm("fma.rn.f32x2 %0, %1, %2, %0;" : "+l"(d) : "l"(a), "l"(b));
}
__device__ __forceinline__ float2 unpack2(unsigned long long v) {
    float2 r;
    asm("mov.b64 {%0, %1}, %2;" : "=f"(r.x), "=f"(r.y) : "l"(v));
    return r;
}

// ---------------------------------------------------------------------------
// Generic fp32 GEMM: C[M,N] = alpha * A[M,K] @ op(B) + bias
//   transB=1: B is [N,K] row-major (C = A @ B^T)
//   transB=0: B is [K,N] row-major (C = A @ B)
// BM=BN=128, BK=8, 256 threads, 8x8 micro-tile computed with packed
// fma.rn.f32x2 (FFMA2): 32 packed FMAs per k-step instead of 64 FFMA.
// B fragments are read straight out of smem as packed u64 pairs (no pack MOVs);
// only the A broadcast needs dup MOVs. Register-prefetch pipeline hides
// global-load latency behind compute.
// Assumes M % 128 == 0, K % 8 == 0, lda/ldb % 4 == 0 (true at all call sites).
// causal=1: skip block if fully above the diagonal (QK scores)
// causal=2: truncate K at m0+128 (PV: attn cols beyond diagonal are zero)
// ---------------------------------------------------------------------------
__global__ __launch_bounds__(256, 2) void gemm128(
    const float* __restrict__ A, const float* __restrict__ B,
    float* __restrict__ C, const float* __restrict__ bias,
    int M, int N, int K, int lda, int ldb, int ldc,
    long long sA, long long sB, long long sC,
    float alpha, int transB, int causal)
{
    const int z = blockIdx.z;
    A += (long long)z * sA;
    B += (long long)z * sB;
    C += (long long)z * sC;

    const int m0 = blockIdx.y * 128;
    const int n0 = blockIdx.x * 128;

    if (causal == 1 && n0 > m0 + 127) return;
    int Kend = K;
    if (causal == 2) Kend = min(K, m0 + 128);

    __shared__ __align__(16) float As[8][128];
    __shared__ __align__(16) float Bs[8][128];

    const int tid = threadIdx.x;
    const int tx  = tid & 15;
    const int ty  = tid >> 4;

    const int arow  = tid >> 1;          // 0..127
    const int akq   = (tid & 1) * 4;     // 0 or 4
    const int bkrow = tid >> 5;          // 0..7   (nn loader)
    const int bnq   = (tid & 31) * 4;    // 0..124 (nn loader)

    // acc[i][jp] holds (C[i][2jp], C[i][2jp+1]) packed; zero bits == (+0,+0)
    unsigned long long acc[8][4];
    #pragma unroll
    for (int i = 0; i < 8; i++)
        #pragma unroll
        for (int j = 0; j < 4; j++) acc[i][j] = 0ULL;

    const float* Aptr = &A[(long long)(m0 + arow) * lda + akq];

    float4 aP, bP;
    // initial prefetch (Kend >= 8 at every call site)
    aP = *reinterpret_cast<const float4*>(Aptr);
    if (transB) {
        const int n = n0 + arow;
        bP = make_float4(0.f, 0.f, 0.f, 0.f);
        if (n < N)
            bP = *reinterpret_cast<const float4*>(&B[(long long)n * ldb + akq]);
    } else {
        const int n = n0 + bnq;
        bP = make_float4(0.f, 0.f, 0.f, 0.f);
        if (n + 3 < N) {
            bP = *reinterpret_cast<const float4*>(&B[(long long)bkrow * ldb + n]);
        } else if (n < N) {
            const float* bp = &B[(long long)bkrow * ldb];
            bP.x = bp[n];
            if (n + 1 < N) bP.y = bp[n + 1];
            if (n + 2 < N) bP.z = bp[n + 2];
        }
    }

    for (int k0 = 0; k0 < Kend; k0 += 8) {
        // ---- commit prefetched tiles to smem ----
        As[akq + 0][arow] = aP.x;
        As[akq + 1][arow] = aP.y;
        As[akq + 2][arow] = aP.z;
        As[akq + 3][arow] = aP.w;
        if (transB) {
            Bs[akq + 0][arow] = bP.x;
            Bs[akq + 1][arow] = bP.y;
            Bs[akq + 2][arow] = bP.z;
            Bs[akq + 3][arow] = bP.w;
        } else {
            *reinterpret_cast<float4*>(&Bs[bkrow][bnq]) = bP;
        }
        __syncthreads();

        // ---- prefetch next iteration while computing this one ----
        const int k1 = k0 + 8;
        if (k1 < Kend) {
            aP = *reinterpret_cast<const float4*>(Aptr + k1);
            if (transB) {
                const int n = n0 + arow;
                bP = make_float4(0.f, 0.f, 0.f, 0.f);
                if (n < N)
                    bP = *reinterpret_cast<const float4*>(&B[(long long)n * ldb + k1 + akq]);
            } else {
                const int n = n0 + bnq;
                bP = make_float4(0.f, 0.f, 0.f, 0.f);
                if (n + 3 < N) {
                    bP = *reinterpret_cast<const float4*>(&B[(long long)(k1 + bkrow) * ldb + n]);
                } else if (n < N) {
                    const float* bp = &B[(long long)(k1 + bkrow) * ldb];
                    bP.x = bp[n];
                    if (n + 1 < N) bP.y = bp[n + 1];
                    if (n + 2 < N) bP.z = bp[n + 2];
                }
            }
        }

        #pragma unroll
        for (int k = 0; k < 8; k++) {
            float4 a0 = *reinterpret_cast<const float4*>(&As[k][ty * 4]);
            float4 a1 = *reinterpret_cast<const float4*>(&As[k][64 + ty * 4]);
            // B pairs read pre-packed from smem (16B-aligned: tx*4 floats)
            ulonglong2 b01 = *reinterpret_cast<const ulonglong2*>(&Bs[k][tx * 4]);
            ulonglong2 b23 = *reinterpret_cast<const ulonglong2*>(&Bs[k][64 + tx * 4]);

            unsigned long long bp2[4];
            bp2[0] = b01.x; bp2[1] = b01.y;
            bp2[2] = b23.x; bp2[3] = b23.y;

            unsigned long long aa[8];
            aa[0] = dup2(a0.x); aa[1] = dup2(a0.y);
            aa[2] = dup2(a0.z); aa[3] = dup2(a0.w);
            aa[4] = dup2(a1.x); aa[5] = dup2(a1.y);
            aa[6] = dup2(a1.z); aa[7] = dup2(a1.w);

            #pragma unroll
            for (int i = 0; i < 8; i++)
                #pragma unroll
                for (int jp = 0; jp < 4; jp++)
                    fma2(acc[i][jp], aa[i], bp2[jp]);
        }
        __syncthreads();
    }

    // ---- epilogue ----
    const bool hasBias = (bias != nullptr);
    #pragma unroll
    for (int ih = 0; ih < 2; ih++) {
        #pragma unroll
        for (int i = 0; i < 4; i++) {
            const int r = m0 + ih * 64 + ty * 4 + i;
            float* Crow = C + (long long)r * ldc;
            #pragma unroll
            for (int jh = 0; jh < 2; jh++) {
                #pragma unroll
                for (int jp = 0; jp < 2; jp++) {
                    const float2 v2 = unpack2(acc[ih * 4 + i][jh * 2 + jp]);
                    const int c = n0 + jh * 64 + tx * 4 + jp * 2;
                    if (c < N) {
                        float vv = alpha * v2.x;
                        if (hasBias) vv += bias[c];
                        Crow[c] = vv;
                    }
                    if (c + 1 < N) {
                        float vv = alpha * v2.y;
                        if (hasBias) vv += bias[c + 1];
                        Crow[c + 1] = vv;
                    }
                }
            }
        }
    }
}

// ---------------------------------------------------------------------------
// RMSNorm over rows: o = g * x * rsqrt(mean(x^2) + eps)
// ---------------------------------------------------------------------------
__global__ void rmsnorm_k(const float* __restrict__ x, float* __restrict__ o,
                          const float* __restrict__ g, int width, int in_ld, int out_ld)
{
    const int r = blockIdx.x;
    const float* row = x + (long long)r * in_ld;
    __shared__ float red[256];
    float s = 0.f;
    for (int i = threadIdx.x; i < width; i += 256) {
        float v = row[i];
        s += v * v;
    }
    red[threadIdx.x] = s;
    __syncthreads();
    for (int st = 128; st > 0; st >>= 1) {
        if (threadIdx.x < st) red[threadIdx.x] += red[threadIdx.x + st];
        __syncthreads();
    }
    const float inv = rsqrtf(red[0] / (float)width + 1e-6f);
    for (int i = threadIdx.x; i < width; i += 256)
        o[(long long)r * out_ld + i] = g[i] * (row[i] * inv);
}

// ---------------------------------------------------------------------------
// RoPE table: cos/sin per (position, freq). 2048 x 32, double-precision trig
// on the f32-rounded angle (matches the f32 reference's angle rounding).
// ---------------------------------------------------------------------------
__global__ void rope_table(const int* __restrict__ pos)
{
    const int s = blockIdx.x;
    const int j = threadIdx.x;          // 0..31
    const double invf = pow(10000.0, -(double)j / 32.0);
    const float  ang  = (float)pos[s] * (float)invf;   // f32 rounding like ref
    g_cos[s * 32 + j] = (float)cos((double)ang);
    g_sin[s * 32 + j] = (float)sin((double)ang);
}

// ---------------------------------------------------------------------------
// Build head-major q_all / k_all (with RoPE) and v tensors.
// RoPE (interleave-to-half + rotate-half):
//   out[j]    = x[2j]   * cos_j - x[2j+1] * sin_j      (j < 32)
//   out[32+j] = x[2j+1] * cos_j + x[2j]   * sin_j
// ---------------------------------------------------------------------------
__global__ void assemble_rope(const float* __restrict__ q, const float* __restrict__ kv,
                              const float* __restrict__ kvd)
{
    const int s = blockIdx.x;

    for (int e = threadIdx.x; e < NH * QD; e += blockDim.x) {
        const int h = e / QD, d = e % QD;
        float qa, ka;
        if (d < NOPE) {
            qa = q [(long long)s * (NH * QD) + h * QD + d];
            ka = kv[(long long)s * (NH * 256) + h * 256 + d];
        } else {
            const int j  = d - NOPE;
            const int jj = (j < 32) ? j : j - 32;
            const float c  = g_cos[s * 32 + jj];
            const float sn = g_sin[s * 32 + jj];
            const long long qb = (long long)s * (NH * QD) + h * QD + NOPE;
            const float qx = q[qb + 2 * jj];
            const float qy = q[qb + 2 * jj + 1];
            const long long kb = (long long)s * KVDN + KVLR;
            const float kx = kvd[kb + 2 * jj];
            const float ky = kvd[kb + 2 * jj + 1];
            if (j < 32) { qa = qx * c - qy * sn; ka = kx * c - ky * sn; }
            else        { qa = qy * c + qx * sn; ka = ky * c + kx * sn; }
        }
        g_qall[((long long)h * SQ + s) * QD + d] = qa;
        g_kall[((long long)h * SQ + s) * QD + d] = ka;
    }

    for (int e = threadIdx.x; e < NH * VDIM; e += blockDim.x) {
        const int h = e / VDIM, d = e % VDIM;
        g_v[((long long)h * SQ + s) * VDIM + d] =
            kv[(long long)s * (NH * 256) + h * 256 + NOPE + d];
    }
}

// ---------------------------------------------------------------------------
// Causal softmax in place; zero-fills masked columns (k > q).
// One 256-thread block per (head, q) row; 2048 columns = 8 per thread.
// ---------------------------------------------------------------------------
__global__ void softmax_causal(float* __restrict__ attn)
{
    const long long row = blockIdx.x;
    const int q = (int)(row % SQ);
    float* p = attn + row * SQ;
    const int valid = q + 1;

    __shared__ float red[256];
    const int t = threadIdx.x;

    float vals[8];
    float mx = -INFINITY;
    #pragma unroll
    for (int i = 0; i < 8; i++) {
        const int k = t + i * 256;
        vals[i] = (k < valid) ? p[k] : -INFINITY;
        mx = fmaxf(mx, vals[i]);
    }
    red[t] = mx;
    __syncthreads();
    for (int st = 128; st > 0; st >>= 1) {
        if (t < st) red[t] = fmaxf(red[t], red[t + st]);
        __syncthreads();
    }
    mx = red[0];
    __syncthreads();

    float sm = 0.f;
    #pragma unroll
    for (int i = 0; i < 8; i++) {
        const float e = (vals[i] == -INFINITY) ? 0.f : expf(vals[i] - mx);
        vals[i] = e;
        sm += e;
    }
    red[t] = sm;
    __syncthreads();
    for (int st = 128; st > 0; st >>= 1) {
        if (t < st) red[t] += red[t + st];
        __syncthreads();
    }
    const float inv = 1.f / red[0];
    #pragma unroll
    for (int i = 0; i < 8; i++) {
        const int k = t + i * 256;
        p[k] = vals[i] * inv;
    }
}

// ---------------------------------------------------------------------------
extern "C" void kernel_launch(void* const* d_in, const int* in_sizes, int n_in,
                              void* d_out, int out_size)
{
    const float* hs       = (const float*)d_in[0];
    const int*   pos      = (const int*)  d_in[1];
    // d_in[2] = causal_mask (bool) — causality derived from indices instead
    const float* Wq_down  = (const float*)d_in[3];
    const float* bq_down  = (const float*)d_in[4];
    const float* gq_norm  = (const float*)d_in[5];
    const float* Wq_up    = (const float*)d_in[6];
    const float* Wkv_down = (const float*)d_in[7];
    const float* bkv_down = (const float*)d_in[8];
    const float* gkv_norm = (const float*)d_in[9];
    const float* Wkv_up   = (const float*)d_in[10];
    const float* Wo       = (const float*)d_in[11];

    float* out  = (float*)d_out;                       // [S, HID]
    float* attn = out + (long long)SQ * HIDD;          // [H, S, S]

    float *qc, *kvd, *q, *kv, *qall, *kall, *v, *ctx;
    cudaGetSymbolAddress((void**)&qc,   g_qc);
    cudaGetSymbolAddress((void**)&kvd,  g_kvd);
    cudaGetSymbolAddress((void**)&q,    g_q);
    cudaGetSymbolAddress((void**)&kv,   g_kv);
    cudaGetSymbolAddress((void**)&qall, g_qall);
    cudaGetSymbolAddress((void**)&kall, g_kall);
    cudaGetSymbolAddress((void**)&v,    g_v);
    cudaGetSymbolAddress((void**)&ctx,  g_ctx);

    const dim3 blk(256);

    // 0) RoPE cos/sin table
    rope_table<<<SQ, 32>>>(pos);

    // 1) qc = hs @ Wq_down^T + bq_down              [2048, 1536]
    gemm128<<<dim3(QLR / 128, SQ / 128, 1), blk>>>(
        hs, Wq_down, qc, bq_down, SQ, QLR, HIDD, HIDD, HIDD, QLR,
        0, 0, 0, 1.f, 1, 0);

    // 2) kvd = hs @ Wkv_down^T + bkv_down           [2048, 576]
    gemm128<<<dim3((KVDN + 127) / 128, SQ / 128, 1), blk>>>(
        hs, Wkv_down, kvd, bkv_down, SQ, KVDN, HIDD, HIDD, HIDD, KVDN,
        0, 0, 0, 1.f, 1, 0);

    // 3) rmsnorm qc (in place) and kvd[:, :512] (in place)
    rmsnorm_k<<<SQ, 256>>>(qc,  qc,  gq_norm,  QLR,  QLR,  QLR);
    rmsnorm_k<<<SQ, 256>>>(kvd, kvd, gkv_norm, KVLR, KVDN, KVDN);

    // 4) q = qc @ Wq_up^T                           [2048, 3072]
    gemm128<<<dim3(NH * QD / 128, SQ / 128, 1), blk>>>(
        qc, Wq_up, q, nullptr, SQ, NH * QD, QLR, QLR, QLR, NH * QD,
        0, 0, 0, 1.f, 1, 0);

    // 5) kv = ckv @ Wkv_up^T                        [2048, 4096]
    gemm128<<<dim3(NH * 256 / 128, SQ / 128, 1), blk>>>(
        kvd, Wkv_up, kv, nullptr, SQ, NH * 256, KVLR, KVDN, KVLR, NH * 256,
        0, 0, 0, 1.f, 1, 0);

    // 6) assemble q_all/k_all (RoPE) and v in head-major layouts
    assemble_rope<<<SQ, 256>>>(q, kv, kvd);

    // 7) scores = (q_all @ k_all^T) / sqrt(QD), per head, causal-block-skip
    const float scale = 1.f / sqrtf((float)QD);
    gemm128<<<dim3(SQ / 128, SQ / 128, NH), blk>>>(
        qall, kall, attn, nullptr, SQ, SQ, QD, QD, QD, SQ,
        (long long)SQ * QD, (long long)SQ * QD, (long long)SQ * SQ,
        scale, 1, 1);

    // 8) causal softmax in place (writes every attn element incl. zeros)
    softmax_causal<<<NH * SQ, 256>>>(attn);

    // 9) ctx = attn @ v, per head, K truncated at the diagonal
    gemm128<<<dim3(1, SQ / 128, NH), blk>>>(
        attn, v, ctx, nullptr, SQ, VDIM, SQ, SQ, VDIM, NH * VDIM,
        (long long)SQ * SQ, (long long)SQ * VDIM, (long long)VDIM,
        1.f, 0, 2);

    // 10) out = ctx @ Wo^T                          [2048, 2048]
    gemm128<<<dim3(HIDD / 128, SQ / 128, 1), blk>>>(
        ctx, Wo, out, nullptr, SQ, HIDD, NH * VDIM, NH * VDIM, NH * VDIM, HIDD,
        0, 0, 0, 1.f, 1, 0);
}

// round 5
// speedup vs baseline: 1.7990x; 1.7990x over previous
#include <cuda_runtime.h>
#include <cuda_bf16.h>
#include <math.h>
#include <stdint.h>

#define SQ    2048
#define HIDD  2048
#define NH    16
#define NOPE  128
#define ROPE  64
#define VDIM  128
#define QD    192   // NOPE + ROPE
#define QLR   1536
#define KVLR  512
#define KVDN  576   // KVLR + ROPE

// GEMM tiling
#define BM    128
#define BN    128
#define BK    16
#define TPB   512
#define LDT   24                      // bf16 row stride (48B): conflict-free ldmatrix
#define TILE_E  (BM * LDT)            // 3072 bf16 per tile array
#define STAGE_E (4 * TILE_E)          // Ah, Al, Bh, Bl
#define SMEM_BYTES (2 * STAGE_E * 2)  // 49152 = 48KB (two stages)

// ---------------- scratch (static device globals; no allocation) ----------------
__device__ __align__(256) float g_qc [SQ * QLR];
__device__ __align__(256) float g_kvd[SQ * KVDN];
__device__ __align__(256) float g_q  [SQ * NH * QD];
__device__ __align__(256) float g_kv [SQ * NH * (NOPE + VDIM)];
__device__ __align__(256) float g_qall[(long long)NH * SQ * QD];
__device__ __align__(256) float g_kall[(long long)NH * SQ * QD];
__device__ __align__(256) float g_vT [(long long)NH * VDIM * SQ];   // V transposed: [h][d][s]
__device__ __align__(256) float g_ctx[SQ * NH * VDIM];
__device__ __align__(256) float g_cos[SQ * 32];
__device__ __align__(256) float g_sin[SQ * 32];

// ---------------- tensor-core primitives ----------------
__device__ __forceinline__ void ldsm4(uint32_t* r, uint32_t addr) {
    asm volatile("ldmatrix.sync.aligned.m8n8.x4.shared.b16 {%0,%1,%2,%3}, [%4];"
        : "=r"(r[0]), "=r"(r[1]), "=r"(r[2]), "=r"(r[3]) : "r"(addr));
}
__device__ __forceinline__ void mma_bf16(float* d, const uint32_t* a,
                                         uint32_t b0, uint32_t b1) {
    asm volatile(
        "mma.sync.aligned.m16n8k16.row.col.f32.bf16.bf16.f32 "
        "{%0,%1,%2,%3}, {%4,%5,%6,%7}, {%8,%9}, {%0,%1,%2,%3};"
        : "+f"(d[0]), "+f"(d[1]), "+f"(d[2]), "+f"(d[3])
        : "r"(a[0]), "r"(a[1]), "r"(a[2]), "r"(a[3]), "r"(b0), "r"(b1));
}

// split float4 -> (hi, lo) bf16 quads packed as uint2 each
__device__ __forceinline__ void split4(float4 v, uint2& hi, uint2& lo) {
    __nv_bfloat16 h0 = __float2bfloat16(v.x), h1 = __float2bfloat16(v.y);
    __nv_bfloat16 h2 = __float2bfloat16(v.z), h3 = __float2bfloat16(v.w);
    __nv_bfloat16 l0 = __float2bfloat16(v.x - __bfloat162float(h0));
    __nv_bfloat16 l1 = __float2bfloat16(v.y - __bfloat162float(h1));
    __nv_bfloat16 l2 = __float2bfloat16(v.z - __bfloat162float(h2));
    __nv_bfloat16 l3 = __float2bfloat16(v.w - __bfloat162float(h3));
    __nv_bfloat162 p;
    p = __halves2bfloat162(h0, h1); hi.x = *reinterpret_cast<uint32_t*>(&p);
    p = __halves2bfloat162(h2, h3); hi.y = *reinterpret_cast<uint32_t*>(&p);
    p = __halves2bfloat162(l0, l1); lo.x = *reinterpret_cast<uint32_t*>(&p);
    p = __halves2bfloat162(l2, l3); lo.y = *reinterpret_cast<uint32_t*>(&p);
}

// ---------------------------------------------------------------------------
// Tensor-core GEMM: C[M,N] = alpha * A[M,K] @ B^T + bias,  B is [N,K] row-major.
// bf16 2-term split (hi+lo), 3 MMAs per product term: hi*hi + hi*lo + lo*hi.
// CTA tile 128x128, 16 warps in a 4x4 grid (warp tile 32x32), k-chunk 16.
// Two-stage smem ping-pong; fp32->bf16 split conversion on the fly.
// Requires M % 128 == 0, K % 16 == 0 (true at all call sites). N guarded.
// causal=1: skip blocks fully above the diagonal. causal=2: Kend = m0+128.
// ---------------------------------------------------------------------------
__global__ __launch_bounds__(TPB, 1) void gemm_mma(
    const float* __restrict__ A, const float* __restrict__ B,
    float* __restrict__ C, const float* __restrict__ bias,
    int M, int N, int K, int lda, int ldb, int ldc,
    long long sA, long long sB, long long sC,
    float alpha, int causal)
{
    extern __shared__ __nv_bfloat16 sm[];

    const int z = blockIdx.z;
    A += (long long)z * sA;
    B += (long long)z * sB;
    C += (long long)z * sC;

    const int m0 = blockIdx.y * BM;
    const int n0 = blockIdx.x * BN;
    if (causal == 1 && n0 > m0 + BM - 1) return;
    const int Kend = (causal == 2) ? min(K, m0 + BM) : K;
    const int nchunks = Kend / BK;

    const int tid  = threadIdx.x;
    const int wid  = tid >> 5;
    const int lane = tid & 31;
    const int wm   = (wid & 3) * 32;    // warp row offset in tile
    const int wn   = (wid >> 2) * 32;   // warp col offset in tile

    // ---- loader mapping: 512 threads cover 128x16 f32 (one float4 each) ----
    const int lrow = tid >> 2;          // 0..127
    const int lcol = (tid & 3) * 4;     // 0,4,8,12
    const float* Ag = A + (long long)(m0 + lrow) * lda + lcol;
    const bool  bvalid = (n0 + lrow) < N;
    const float* Bg = bvalid ? (B + (long long)(n0 + lrow) * ldb + lcol) : B;
    const int soff = lrow * LDT + lcol; // smem element offset (8B-aligned *2)

    uint32_t smbase = (uint32_t)__cvta_generic_to_shared(sm);

    // ldmatrix per-lane element offsets within a tile array
    const int aoff = (wm + (lane & 15)) * LDT + (lane >> 4) * 8;
    const int boff = (wn + (lane & 15)) * LDT + (lane >> 4) * 8;

    float acc[2][4][4];
    #pragma unroll
    for (int i = 0; i < 2; i++)
        #pragma unroll
        for (int j = 0; j < 4; j++)
            #pragma unroll
            for (int l = 0; l < 4; l++) acc[i][j][l] = 0.f;

    // ---- preload chunk 0 into stage 0 ----
    float4 fa = *reinterpret_cast<const float4*>(Ag);
    float4 fb = make_float4(0.f, 0.f, 0.f, 0.f);
    if (bvalid) fb = *reinterpret_cast<const float4*>(Bg);
    {
        uint2 hi, lo;
        split4(fa, hi, lo);
        *reinterpret_cast<uint2*>(&sm[0 * TILE_E + soff]) = hi;
        *reinterpret_cast<uint2*>(&sm[1 * TILE_E + soff]) = lo;
        split4(fb, hi, lo);
        *reinterpret_cast<uint2*>(&sm[2 * TILE_E + soff]) = hi;
        *reinterpret_cast<uint2*>(&sm[3 * TILE_E + soff]) = lo;
    }
    __syncthreads();

    for (int ic = 0; ic < nchunks; ic++) {
        const int st = ic & 1;
        const uint32_t stB = smbase + (uint32_t)(st * STAGE_E) * 2u;

        // prefetch next chunk (global -> regs) before compute
        const bool more = (ic + 1) < nchunks;
        if (more) {
            const int k1 = (ic + 1) * BK;
            fa = *reinterpret_cast<const float4*>(Ag + k1);
            if (bvalid) fb = *reinterpret_cast<const float4*>(Bg + k1);
        }

        // ---- fragments + MMAs on current stage ----
        uint32_t af[2][4], bh[2][4], bl[2][4];
        ldsm4(af[0], stB + 2u * (0 * TILE_E + aoff));
        ldsm4(af[1], stB + 2u * (0 * TILE_E + aoff + 16 * LDT));
        ldsm4(bh[0], stB + 2u * (2 * TILE_E + boff));
        ldsm4(bh[1], stB + 2u * (2 * TILE_E + boff + 16 * LDT));
        ldsm4(bl[0], stB + 2u * (3 * TILE_E + boff));
        ldsm4(bl[1], stB + 2u * (3 * TILE_E + boff + 16 * LDT));

        #pragma unroll
        for (int mb = 0; mb < 2; mb++)
            #pragma unroll
            for (int nb = 0; nb < 4; nb++) {
                const int gI = nb >> 1, hI = nb & 1;
                mma_bf16(acc[mb][nb], af[mb], bh[gI][hI], bh[gI][2 + hI]);  // hi*hi
                mma_bf16(acc[mb][nb], af[mb], bl[gI][hI], bl[gI][2 + hI]);  // hi*lo
            }

        ldsm4(af[0], stB + 2u * (1 * TILE_E + aoff));
        ldsm4(af[1], stB + 2u * (1 * TILE_E + aoff + 16 * LDT));
        #pragma unroll
        for (int mb = 0; mb < 2; mb++)
            #pragma unroll
            for (int nb = 0; nb < 4; nb++) {
                const int gI = nb >> 1, hI = nb & 1;
                mma_bf16(acc[mb][nb], af[mb], bh[gI][hI], bh[gI][2 + hI]);  // lo*hi
            }

        // ---- convert + store prefetched chunk into the other stage ----
        if (more) {
            __nv_bfloat16* nsm = sm + (st ^ 1) * STAGE_E;
            uint2 hi, lo;
            split4(fa, hi, lo);
            *reinterpret_cast<uint2*>(&nsm[0 * TILE_E + soff]) = hi;
            *reinterpret_cast<uint2*>(&nsm[1 * TILE_E + soff]) = lo;
            split4(fb, hi, lo);
            *reinterpret_cast<uint2*>(&nsm[2 * TILE_E + soff]) = hi;
            *reinterpret_cast<uint2*>(&nsm[3 * TILE_E + soff]) = lo;
        }
        __syncthreads();
    }

    // ---- epilogue ----
    const bool hasBias = (bias != nullptr);
    const int gI = lane >> 2;
    const int t2 = (lane & 3) * 2;
    #pragma unroll
    for (int mb = 0; mb < 2; mb++) {
        #pragma unroll
        for (int nb = 0; nb < 4; nb++) {
            const int r = m0 + wm + mb * 16 + gI;
            const int c = n0 + wn + nb * 8 + t2;
            float* Cr0 = C + (long long)r * ldc;
            float* Cr1 = C + (long long)(r + 8) * ldc;
            if (c < N) {
                float b0 = hasBias ? bias[c] : 0.f;
                Cr0[c] = alpha * acc[mb][nb][0] + b0;
                Cr1[c] = alpha * acc[mb][nb][2] + b0;
            }
            if (c + 1 < N) {
                float b1 = hasBias ? bias[c + 1] : 0.f;
                Cr0[c + 1] = alpha * acc[mb][nb][1] + b1;
                Cr1[c + 1] = alpha * acc[mb][nb][3] + b1;
            }
        }
    }
}

// ---------------------------------------------------------------------------
// RMSNorm over rows: o = g * x * rsqrt(mean(x^2) + eps)
// ---------------------------------------------------------------------------
__global__ void rmsnorm_k(const float* __restrict__ x, float* __restrict__ o,
                          const float* __restrict__ g, int width, int in_ld, int out_ld)
{
    const int r = blockIdx.x;
    const float* row = x + (long long)r * in_ld;
    __shared__ float red[256];
    float s = 0.f;
    for (int i = threadIdx.x; i < width; i += 256) {
        float v = row[i];
        s += v * v;
    }
    red[threadIdx.x] = s;
    __syncthreads();
    for (int st = 128; st > 0; st >>= 1) {
        if (threadIdx.x < st) red[threadIdx.x] += red[threadIdx.x + st];
        __syncthreads();
    }
    const float inv = rsqrtf(red[0] / (float)width + 1e-6f);
    for (int i = threadIdx.x; i < width; i += 256)
        o[(long long)r * out_ld + i] = g[i] * (row[i] * inv);
}

// ---------------------------------------------------------------------------
// RoPE table: cos/sin per (position, freq), double trig on f32-rounded angle.
// ---------------------------------------------------------------------------
__global__ void rope_table(const int* __restrict__ pos)
{
    const int s = blockIdx.x;
    const int j = threadIdx.x;          // 0..31
    const double invf = pow(10000.0, -(double)j / 32.0);
    const float  ang  = (float)pos[s] * (float)invf;   // f32 rounding like ref
    g_cos[s * 32 + j] = (float)cos((double)ang);
    g_sin[s * 32 + j] = (float)sin((double)ang);
}

// ---------------------------------------------------------------------------
// Build head-major q_all / k_all (with RoPE).
// ---------------------------------------------------------------------------
__global__ void assemble_rope(const float* __restrict__ q, const float* __restrict__ kv,
                              const float* __restrict__ kvd)
{
    const int s = blockIdx.x;

    for (int e = threadIdx.x; e < NH * QD; e += blockDim.x) {
        const int h = e / QD, d = e % QD;
        float qa, ka;
        if (d < NOPE) {
            qa = q [(long long)s * (NH * QD) + h * QD + d];
            ka = kv[(long long)s * (NH * 256) + h * 256 + d];
        } else {
            const int j  = d - NOPE;
            const int jj = (j < 32) ? j : j - 32;
            const float c  = g_cos[s * 32 + jj];
            const float sn = g_sin[s * 32 + jj];
            const long long qb = (long long)s * (NH * QD) + h * QD + NOPE;
            const float qx = q[qb + 2 * jj];
            const float qy = q[qb + 2 * jj + 1];
            const long long kb = (long long)s * KVDN + KVLR;
            const float kx = kvd[kb + 2 * jj];
            const float ky = kvd[kb + 2 * jj + 1];
            if (j < 32) { qa = qx * c - qy * sn; ka = kx * c - ky * sn; }
            else        { qa = qy * c + qx * sn; ka = ky * c + kx * sn; }
        }
        g_qall[((long long)h * SQ + s) * QD + d] = qa;
        g_kall[((long long)h * SQ + s) * QD + d] = ka;
    }
}

// ---------------------------------------------------------------------------
// V transpose: g_vT[h][d][s] = kv[s][h*256 + 128 + d]  (tiled, coalesced both sides)
// ---------------------------------------------------------------------------
__global__ void transpose_v(const float* __restrict__ kv)
{
    __shared__ float t[32][33];
    const int h  = blockIdx.z;
    const int S0 = blockIdx.x * 32;
    const int D0 = blockIdx.y * 32;
    const int tx = threadIdx.x, ty = threadIdx.y;   // 32 x 8

    #pragma unroll
    for (int j = 0; j < 4; j++) {
        const int s = S0 + ty + j * 8;
        t[ty + j * 8][tx] = kv[(long long)s * (NH * 256) + h * 256 + NOPE + D0 + tx];
    }
    __syncthreads();
    #pragma unroll
    for (int j = 0; j < 4; j++) {
        const int d = D0 + ty + j * 8;
        g_vT[((long long)h * VDIM + d) * SQ + S0 + tx] = t[tx][ty + j * 8];
    }
}

// ---------------------------------------------------------------------------
// Causal softmax in place; zero-fills masked columns (k > q).
// ---------------------------------------------------------------------------
__global__ void softmax_causal(float* __restrict__ attn)
{
    const long long row = blockIdx.x;
    const int q = (int)(row % SQ);
    float* p = attn + row * SQ;
    const int valid = q + 1;

    __shared__ float red[256];
    const int t = threadIdx.x;

    float vals[8];
    float mx = -INFINITY;
    #pragma unroll
    for (int i = 0; i < 8; i++) {
        const int k = t + i * 256;
        vals[i] = (k < valid) ? p[k] : -INFINITY;
        mx = fmaxf(mx, vals[i]);
    }
    red[t] = mx;
    __syncthreads();
    for (int st = 128; st > 0; st >>= 1) {
        if (t < st) red[t] = fmaxf(red[t], red[t + st]);
        __syncthreads();
    }
    mx = red[0];
    __syncthreads();

    float sm = 0.f;
    #pragma unroll
    for (int i = 0; i < 8; i++) {
        const float e = (vals[i] == -INFINITY) ? 0.f : expf(vals[i] - mx);
        vals[i] = e;
        sm += e;
    }
    red[t] = sm;
    __syncthreads();
    for (int st = 128; st > 0; st >>= 1) {
        if (t < st) red[t] += red[t + st];
        __syncthreads();
    }
    const float inv = 1.f / red[0];
    #pragma unroll
    for (int i = 0; i < 8; i++) {
        const int k = t + i * 256;
        p[k] = vals[i] * inv;
    }
}

// ---------------------------------------------------------------------------
extern "C" void kernel_launch(void* const* d_in, const int* in_sizes, int n_in,
                              void* d_out, int out_size)
{
    const float* hs       = (const float*)d_in[0];
    const int*   pos      = (const int*)  d_in[1];
    // d_in[2] = causal_mask (bool) — causality derived from indices instead
    const float* Wq_down  = (const float*)d_in[3];
    const float* bq_down  = (const float*)d_in[4];
    const float* gq_norm  = (const float*)d_in[5];
    const float* Wq_up    = (const float*)d_in[6];
    const float* Wkv_down = (const float*)d_in[7];
    const float* bkv_down = (const float*)d_in[8];
    const float* gkv_norm = (const float*)d_in[9];
    const float* Wkv_up   = (const float*)d_in[10];
    const float* Wo       = (const float*)d_in[11];

    float* out  = (float*)d_out;                       // [S, HID]
    float* attn = out + (long long)SQ * HIDD;          // [H, S, S]

    float *qc, *kvd, *q, *kv, *qall, *kall, *vT, *ctx;
    cudaGetSymbolAddress((void**)&qc,   g_qc);
    cudaGetSymbolAddress((void**)&kvd,  g_kvd);
    cudaGetSymbolAddress((void**)&q,    g_q);
    cudaGetSymbolAddress((void**)&kv,   g_kv);
    cudaGetSymbolAddress((void**)&qall, g_qall);
    cudaGetSymbolAddress((void**)&kall, g_kall);
    cudaGetSymbolAddress((void**)&vT,   g_vT);
    cudaGetSymbolAddress((void**)&ctx,  g_ctx);

    const dim3 blk(TPB);

    // 0) RoPE cos/sin table
    rope_table<<<SQ, 32>>>(pos);

    // 1) qc = hs @ Wq_down^T + bq_down              [2048, 1536]
    gemm_mma<<<dim3(QLR / BN, SQ / BM, 1), blk, SMEM_BYTES>>>(
        hs, Wq_down, qc, bq_down, SQ, QLR, HIDD, HIDD, HIDD, QLR,
        0, 0, 0, 1.f, 0);

    // 2) kvd = hs @ Wkv_down^T + bkv_down           [2048, 576]
    gemm_mma<<<dim3((KVDN + BN - 1) / BN, SQ / BM, 1), blk, SMEM_BYTES>>>(
        hs, Wkv_down, kvd, bkv_down, SQ, KVDN, HIDD, HIDD, HIDD, KVDN,
        0, 0, 0, 1.f, 0);

    // 3) rmsnorm qc (in place) and kvd[:, :512] (in place)
    rmsnorm_k<<<SQ, 256>>>(qc,  qc,  gq_norm,  QLR,  QLR,  QLR);
    rmsnorm_k<<<SQ, 256>>>(kvd, kvd, gkv_norm, KVLR, KVDN, KVDN);

    // 4) q = qc @ Wq_up^T                           [2048, 3072]
    gemm_mma<<<dim3(NH * QD / BN, SQ / BM, 1), blk, SMEM_BYTES>>>(
        qc, Wq_up, q, nullptr, SQ, NH * QD, QLR, QLR, QLR, NH * QD,
        0, 0, 0, 1.f, 0);

    // 5) kv = ckv @ Wkv_up^T                        [2048, 4096]
    gemm_mma<<<dim3(NH * 256 / BN, SQ / BM, 1), blk, SMEM_BYTES>>>(
        kvd, Wkv_up, kv, nullptr, SQ, NH * 256, KVLR, KVDN, KVLR, NH * 256,
        0, 0, 0, 1.f, 0);

    // 6) assemble q_all/k_all (RoPE); transpose V to [h][d][s]
    assemble_rope<<<SQ, 256>>>(q, kv, kvd);
    transpose_v<<<dim3(SQ / 32, VDIM / 32, NH), dim3(32, 8)>>>(kv);

    // 7) scores = (q_all @ k_all^T) / sqrt(QD), per head, causal-block-skip
    const float scale = 1.f / sqrtf((float)QD);
    gemm_mma<<<dim3(SQ / BN, SQ / BM, NH), blk, SMEM_BYTES>>>(
        qall, kall, attn, nullptr, SQ, SQ, QD, QD, QD, SQ,
        (long long)SQ * QD, (long long)SQ * QD, (long long)SQ * SQ,
        scale, 1);

    // 8) causal softmax in place (writes every attn element incl. zeros)
    softmax_causal<<<NH * SQ, 256>>>(attn);

    // 9) ctx = attn @ vT^T, per head, K truncated at the diagonal
    gemm_mma<<<dim3(1, SQ / BM, NH), blk, SMEM_BYTES>>>(
        attn, vT, ctx, nullptr, SQ, VDIM, SQ, SQ, SQ, NH * VDIM,
        (long long)SQ * SQ, (long long)VDIM * SQ, (long long)VDIM,
        1.f, 2);

    // 10) out = ctx @ Wo^T                          [2048, 2048]
    gemm_mma<<<dim3(HIDD / BN, SQ / BM, 1), blk, SMEM_BYTES>>>(
        ctx, Wo, out, nullptr, SQ, HIDD, NH * VDIM, NH * VDIM, NH * VDIM, HIDD,
        0, 0, 0, 1.f, 0);
}